// round 2
// baseline (speedup 1.0000x reference)
#include <cuda_runtime.h>
#include <math.h>

// Problem constants
constexpr int cB = 64, cT = 256, cE = 128, cDEG = 8, cHID = 100;
constexpr int cTM1 = 255, cNBUCKET = 288;

// GEMM tiling
constexpr int BM = 64, BN = 64, BK = 16;

// ---------------- device scratch (no allocation allowed) ----------------
__device__ float g_X [cB*cT*cE];     // gathered embeddings
__device__ float g_Q [cB*cT*cE];
__device__ float g_K [cB*cT*cE];
__device__ float g_V [cB*cT*cE];
__device__ float g_S [cB*cT*cT];     // scores / probs
__device__ float g_AH[cB*cT*cE];     // attention output before Wo
__device__ float g_Hc[cB*cT*cHID];   // (AH @ (Wo@W1[:128]))
__device__ float g_WoW1[cE*cHID];
__device__ float g_Db[cB*cHID];
__device__ float g_Ad[cHID], g_Ax[cHID], g_Ay[cHID], g_Cv[cHID];
__device__ float g_u1[25], g_w1b[25];
__device__ float g_stats[3];         // sum, sumsq, cnt
__device__ float g_white[2];         // mean, inv(std+1e-6)
__device__ float g_per[cB];

// ---------------- init ----------------
__global__ void init_kernel() {
    int t = threadIdx.x;
    if (t < cB) g_per[t] = 0.f;
    if (t < 3)  g_stats[t] = 0.f;
}

// ---------------- embedding gather ----------------
__global__ void gather_kernel(const int* __restrict__ xs, const float* __restrict__ emb) {
    int row = blockIdx.x;
    int e = threadIdx.x;
    g_X[row*cE + e] = emb[(long)xs[row]*cE + e];
}

// ---------------- generic NN GEMM: C = A @ B  (row-major) ----------------
__global__ void gemm_nn(const float* __restrict__ A, const float* __restrict__ Bm,
                        float* __restrict__ C,
                        int M, int N, int K, int lda, int ldb, int ldc,
                        long long sA, long long sB, long long sC, int causal) {
    long long bz = blockIdx.z;
    A  += bz * sA;  Bm += bz * sB;  C += bz * sC;
    int m0 = blockIdx.y * BM, n0 = blockIdx.x * BN;
    __shared__ float As[BM][BK];
    __shared__ float Bs[BK][BN];
    int tx = threadIdx.x, ty = threadIdx.y;
    int tid = ty*16 + tx;
    float acc[4][4] = {};
    int kEnd = causal ? min(K, m0 + BM) : K;
    for (int k0 = 0; k0 < kEnd; k0 += BK) {
        #pragma unroll
        for (int i = 0; i < 4; i++) {
            int idx = tid + i*256;
            int r = idx >> 4, c = idx & 15;
            As[r][c] = A[(long)(m0+r)*lda + k0 + c];
        }
        #pragma unroll
        for (int i = 0; i < 4; i++) {
            int idx = tid + i*256;
            int r = idx >> 6, c = idx & 63;
            Bs[r][c] = (n0 + c < N) ? Bm[(long)(k0+r)*ldb + n0 + c] : 0.f;
        }
        __syncthreads();
        #pragma unroll
        for (int kk = 0; kk < BK; kk++) {
            float a[4], b[4];
            #pragma unroll
            for (int i = 0; i < 4; i++) a[i] = As[ty*4+i][kk];
            #pragma unroll
            for (int j = 0; j < 4; j++) b[j] = Bs[kk][tx*4+j];
            #pragma unroll
            for (int i = 0; i < 4; i++)
                #pragma unroll
                for (int j = 0; j < 4; j++)
                    acc[i][j] += a[i]*b[j];
        }
        __syncthreads();
    }
    #pragma unroll
    for (int i = 0; i < 4; i++) {
        int m = m0 + ty*4 + i;
        #pragma unroll
        for (int j = 0; j < 4; j++) {
            int n = n0 + tx*4 + j;
            if (n < N) C[(long)m*ldc + n] = acc[i][j];
        }
    }
}

// ---------------- NT GEMM: C[m,n] = sum_k A[m,k]*B[n,k] ----------------
__global__ void gemm_nt(const float* __restrict__ A, const float* __restrict__ Bm,
                        float* __restrict__ C,
                        int M, int N, int K, int lda, int ldb, int ldc,
                        long long sA, long long sB, long long sC, int causal_skip) {
    int m0 = blockIdx.y * BM, n0 = blockIdx.x * BN;
    if (causal_skip && n0 >= m0 + BM) return;   // entire tile masked (k > q)
    long long bz = blockIdx.z;
    A  += bz * sA;  Bm += bz * sB;  C += bz * sC;
    __shared__ float As[BM][BK];
    __shared__ float Bs[BK][BN+1];
    int tx = threadIdx.x, ty = threadIdx.y;
    int tid = ty*16 + tx;
    float acc[4][4] = {};
    for (int k0 = 0; k0 < K; k0 += BK) {
        #pragma unroll
        for (int i = 0; i < 4; i++) {
            int idx = tid + i*256;
            int r = idx >> 4, c = idx & 15;
            As[r][c] = A[(long)(m0+r)*lda + k0 + c];
        }
        #pragma unroll
        for (int i = 0; i < 4; i++) {
            int idx = tid + i*256;
            int r = idx >> 4, c = idx & 15;   // r: n-offset, c: k-offset
            Bs[c][r] = (n0 + r < N) ? Bm[(long)(n0+r)*ldb + k0 + c] : 0.f;
        }
        __syncthreads();
        #pragma unroll
        for (int kk = 0; kk < BK; kk++) {
            float a[4], b[4];
            #pragma unroll
            for (int i = 0; i < 4; i++) a[i] = As[ty*4+i][kk];
            #pragma unroll
            for (int j = 0; j < 4; j++) b[j] = Bs[kk][tx*4+j];
            #pragma unroll
            for (int i = 0; i < 4; i++)
                #pragma unroll
                for (int j = 0; j < 4; j++)
                    acc[i][j] += a[i]*b[j];
        }
        __syncthreads();
    }
    #pragma unroll
    for (int i = 0; i < 4; i++) {
        int m = m0 + ty*4 + i;
        #pragma unroll
        for (int j = 0; j < 4; j++) {
            int n = n0 + tx*4 + j;
            if (n < N) C[(long)m*ldc + n] = acc[i][j];
        }
    }
}

// ---------------- masked softmax over key dim ----------------
__global__ void softmax_kernel(const int* __restrict__ lengths) {
    int wid = threadIdx.x >> 5, lane = threadIdx.x & 31;
    int r = blockIdx.x*8 + wid;            // r = b*256 + q
    int b = r >> 8, q = r & 255;
    int len = lengths[b];
    int kmax = min(q + 1, len);            // unmasked: k < kmax
    const float scale = 0.08838834764831845f;  // 1/sqrt(128)
    float* Srow = g_S + (long)r * cT;
    float sv[8];
    float m = -3.0e38f;
    #pragma unroll
    for (int ii = 0; ii < 8; ii++) {
        int k = lane + ii*32;
        float v = (k < kmax) ? Srow[k]*scale : -3.0e38f;
        sv[ii] = v;
        m = fmaxf(m, v);
    }
    for (int o = 16; o > 0; o >>= 1) m = fmaxf(m, __shfl_xor_sync(0xffffffffu, m, o));
    float s = 0.f;
    #pragma unroll
    for (int ii = 0; ii < 8; ii++) {
        int k = lane + ii*32;
        float e = (k < kmax) ? expf(sv[ii] - m) : 0.f;
        sv[ii] = e; s += e;
    }
    for (int o = 16; o > 0; o >>= 1) s += __shfl_xor_sync(0xffffffffu, s, o);
    float inv = 1.f / s;
    #pragma unroll
    for (int ii = 0; ii < 8; ii++) {
        int k = lane + ii*32;
        Srow[k] = sv[ii] * inv;
    }
}

// ---------------- fold Wo @ om_W1[0:128,:] ----------------
__global__ void wow1_kernel(const float* __restrict__ Wo, const float* __restrict__ W1) {
    int i = blockIdx.x, j = threadIdx.x;   // j < 100
    float s = 0.f;
    for (int e = 0; e < cE; e++) s += Wo[i*cE + e] * W1[e*cHID + j];
    g_WoW1[i*cHID + j] = s;
}

// ---------------- D_b = emb[dest_b] @ om_W1[228:356,:] ----------------
__global__ void db_kernel(const int* __restrict__ dest, const float* __restrict__ emb,
                          const float* __restrict__ W1) {
    int b = blockIdx.x, j = threadIdx.x;
    int d = dest[b];
    float s = 0.f;
    for (int e = 0; e < cE; e++) s += emb[(long)d*cE + e] * W1[(228+e)*cHID + j];
    g_Db[b*cHID + j] = s;
}

// ---------------- small precomputed vectors ----------------
__global__ void consts_kernel(const float* __restrict__ distW, const float* __restrict__ distb,
                              const float* __restrict__ dirW,  const float* __restrict__ dirb,
                              const float* __restrict__ ttW,   const float* __restrict__ ttb,
                              const float* __restrict__ obW1,  const float* __restrict__ omb1,
                              const float* __restrict__ W1) {
    int j = threadIdx.x;
    if (j < cHID) {
        float ad = 0, ax = 0, ay = 0, cv = omb1[j];
        for (int f = 0; f < 50; f++) {
            float wd = W1[(128+f)*cHID + j];
            float wr = W1[(178+f)*cHID + j];
            ad += distW[f]*wd;  cv += distb[f]*wd;
            ax += dirW[f]*wr;   ay += dirW[50+f]*wr;  cv += dirb[f]*wr;
        }
        g_Ad[j] = ad; g_Ax[j] = ax; g_Ay[j] = ay; g_Cv[j] = cv;
    }
    if (j < 25) {
        float u = 0, w = 0;
        for (int f = 0; f < 50; f++) {
            u += ttW[f]*obW1[f*25 + j];
            w += ttb[f]*obW1[f*25 + j];
        }
        g_u1[j] = u; g_w1b[j] = w;
    }
}

// ---------------- masked travel-time statistics ----------------
__global__ void stats_kernel(const int* __restrict__ xs, const int* __restrict__ lengths,
                             const int* __restrict__ adj, const int* __restrict__ seg,
                             const float* __restrict__ TD, const int* __restrict__ stp) {
    int b = blockIdx.x, tid = threadIdx.x;
    int len = lengths[b], st = stp[0];
    float s = 0.f, ss = 0.f, c = 0.f;
    for (int i = tid; i < cTM1*cDEG; i += 256) {
        int t = i >> 3;
        if (t >= len - 1) continue;
        int d = i & 7;
        int x = xs[b*cT + t];
        int a = adj[x*cDEG + d];
        if (a != 0) {
            float tt = TD[(long)seg[x*cDEG + d]*cNBUCKET + st];
            s += tt; ss += tt*tt; c += 1.f;
        }
    }
    __shared__ float r0[256], r1[256], r2[256];
    r0[tid] = s; r1[tid] = ss; r2[tid] = c;
    __syncthreads();
    for (int o = 128; o > 0; o >>= 1) {
        if (tid < o) { r0[tid] += r0[tid+o]; r1[tid] += r1[tid+o]; r2[tid] += r2[tid+o]; }
        __syncthreads();
    }
    if (tid == 0) {
        atomicAdd(&g_stats[0], r0[0]);
        atomicAdd(&g_stats[1], r1[0]);
        atomicAdd(&g_stats[2], r2[0]);
    }
}

__global__ void fin_stats_kernel() {
    float s = g_stats[0], ss = g_stats[1], c = g_stats[2];
    float mean = s / c;
    float var = (ss - c*mean*mean) / (c - 1.f);
    g_white[0] = mean;
    g_white[1] = 1.f / (sqrtf(var) + 1e-6f);
}

// ---------------- fused per-(b,t) MLP + neighbor softmax + NLL ----------------
__global__ void mlp_kernel(const int* __restrict__ xs, const int* __restrict__ lengths,
                           const int* __restrict__ acts, const int* __restrict__ dest,
                           const int* __restrict__ adj, const int* __restrict__ seg,
                           const int* __restrict__ stp, const float* __restrict__ loc,
                           const float* __restrict__ TD,
                           const float* __restrict__ W2, const float* __restrict__ b2,
                           const float* __restrict__ W3, const float* __restrict__ b3,
                           const float* __restrict__ obb1, const float* __restrict__ obW2,
                           const float* __restrict__ obb2) {
    int b = blockIdx.y, t = blockIdx.x;
    int len = lengths[b];
    if (t >= len - 1) return;

    __shared__ float sW2[cHID*50];
    __shared__ float sh1[cDEG][cHID];
    __shared__ float sBase[cHID], sAd[cHID], sAx[cHID], sAy[cHID];
    __shared__ float sW3[50], sb2[50];
    __shared__ float su1[25], sw1b[25], sobW2[25], sobb1[25];
    __shared__ float slog[cDEG];

    int tid = threadIdx.x;
    for (int i = tid; i < cHID*50; i += 256) sW2[i] = W2[i];
    if (tid < cHID) {
        sBase[tid] = g_Hc[(long)(b*cT + t)*cHID + tid] + g_Db[b*cHID + tid] + g_Cv[tid];
        sAd[tid] = g_Ad[tid]; sAx[tid] = g_Ax[tid]; sAy[tid] = g_Ay[tid];
    }
    if (tid < 50) { sW3[tid] = W3[tid]; sb2[tid] = b2[tid]; }
    if (tid < 25) { su1[tid] = g_u1[tid]; sw1b[tid] = g_w1b[tid];
                    sobW2[tid] = obW2[tid]; sobb1[tid] = obb1[tid]; }
    __syncthreads();

    int d = tid >> 5, lane = tid & 31;
    int x = xs[b*cT + t];
    int nb = adj[x*cDEG + d];
    float nx = loc[nb*2], ny = loc[nb*2 + 1];
    int db_ = dest[b];
    float dx = loc[db_*2], dy = loc[db_*2 + 1];
    float cx = loc[x*2], cy = loc[x*2 + 1];
    float dist = (fabsf(nx - dx) + fabsf(ny - dy)) * 100.f;
    float vx = nx - cx, vy = ny - cy;
    float inv = 1.f / (sqrtf(vx*vx + vy*vy) + 1e-8f);
    float ux = vx*inv, uy = vy*inv;

    for (int j = lane; j < cHID; j += 32) {
        float h = sBase[j] + dist*sAd[j] + ux*sAx[j] + uy*sAy[j];
        sh1[d][j] = fmaxf(h, 0.f);
    }
    __syncwarp();

    float part = 0.f;
    for (int i = lane; i < 50; i += 32) {
        float acc = sb2[i];
        #pragma unroll 4
        for (int j = 0; j < cHID; j++) acc += sh1[d][j] * sW2[j*50 + i];
        part += fmaxf(acc, 0.f) * sW3[i];
    }

    // ob branch (collapsed)
    float mf = (nb != 0) ? 1.f : 0.f;
    float tt = TD[(long)seg[x*cDEG + d]*cNBUCKET + stp[0]];
    float ttw = (tt - g_white[0]) * g_white[1];
    for (int i = lane; i < 25; i += 32) {
        float z = mf*(ttw*su1[i] + sw1b[i]) + sobb1[i];
        part += fmaxf(z, 0.f) * sobW2[i];
    }

    for (int o = 16; o > 0; o >>= 1) part += __shfl_xor_sync(0xffffffffu, part, o);
    if (lane == 0) slog[d] = part + b3[0] + obb2[0];
    __syncthreads();

    if (tid == 0) {
        float m = slog[0];
        #pragma unroll
        for (int i = 1; i < cDEG; i++) m = fmaxf(m, slog[i]);
        float s = 0.f;
        #pragma unroll
        for (int i = 0; i < cDEG; i++) s += expf(slog[i] - m);
        int a = acts[b*cTM1 + t];
        float nll = (m + logf(s)) - slog[a];
        atomicAdd(&g_per[b], nll);
    }
}

// ---------------- final reduce ----------------
__global__ void final_kernel(const int* __restrict__ lengths, float* __restrict__ out) {
    __shared__ float r[64];
    int t = threadIdx.x;
    r[t] = g_per[t] / (float)(lengths[t] - 1);
    __syncthreads();
    for (int o = 32; o > 0; o >>= 1) {
        if (t < o) r[t] += r[t + o];
        __syncthreads();
    }
    if (t == 0) out[0] = r[0];
}

// ---------------- launch ----------------
extern "C" void kernel_launch(void* const* d_in, const int* in_sizes, int n_in,
                              void* d_out, int out_size) {
    const int*   xs      = (const int*)  d_in[0];
    const int*   lengths = (const int*)  d_in[1];
    const int*   acts    = (const int*)  d_in[2];
    const int*   dest    = (const int*)  d_in[3];
    const int*   adj     = (const int*)  d_in[4];
    const int*   seg     = (const int*)  d_in[5];
    const int*   stp     = (const int*)  d_in[6];
    const float* loc     = (const float*)d_in[7];
    const float* TD      = (const float*)d_in[8];
    const float* emb     = (const float*)d_in[9];
    const float* Wq      = (const float*)d_in[10];
    const float* Wk      = (const float*)d_in[11];
    const float* Wv      = (const float*)d_in[12];
    const float* Wo      = (const float*)d_in[13];
    const float* distW   = (const float*)d_in[14];
    const float* distb   = (const float*)d_in[15];
    const float* dirW    = (const float*)d_in[16];
    const float* dirb    = (const float*)d_in[17];
    const float* ttW     = (const float*)d_in[18];
    const float* ttb     = (const float*)d_in[19];
    const float* obW1    = (const float*)d_in[20];
    const float* obb1    = (const float*)d_in[21];
    const float* obW2    = (const float*)d_in[22];
    const float* obb2    = (const float*)d_in[23];
    const float* W1      = (const float*)d_in[24];
    const float* omb1    = (const float*)d_in[25];
    const float* W2      = (const float*)d_in[26];
    const float* b2      = (const float*)d_in[27];
    const float* W3      = (const float*)d_in[28];
    const float* b3      = (const float*)d_in[29];

    float *pX, *pQ, *pK, *pV, *pS, *pAH, *pHc, *pWoW1;
    cudaGetSymbolAddress((void**)&pX,  g_X);
    cudaGetSymbolAddress((void**)&pQ,  g_Q);
    cudaGetSymbolAddress((void**)&pK,  g_K);
    cudaGetSymbolAddress((void**)&pV,  g_V);
    cudaGetSymbolAddress((void**)&pS,  g_S);
    cudaGetSymbolAddress((void**)&pAH, g_AH);
    cudaGetSymbolAddress((void**)&pHc, g_Hc);
    cudaGetSymbolAddress((void**)&pWoW1, g_WoW1);

    dim3 thr(16, 16);
    const int MT = cB*cT;  // 16384

    init_kernel<<<1, 64>>>();
    gather_kernel<<<MT, cE>>>(xs, emb);

    // Q, K, V = X @ W
    gemm_nn<<<dim3(cE/BN, MT/BM, 1), thr>>>(pX, Wq, pQ, MT, cE, cE, cE, cE, cE, 0, 0, 0, 0);
    gemm_nn<<<dim3(cE/BN, MT/BM, 1), thr>>>(pX, Wk, pK, MT, cE, cE, cE, cE, cE, 0, 0, 0, 0);
    gemm_nn<<<dim3(cE/BN, MT/BM, 1), thr>>>(pX, Wv, pV, MT, cE, cE, cE, cE, cE, 0, 0, 0, 0);

    // S_b = Q_b @ K_b^T  (causal tile skip)
    gemm_nt<<<dim3(cT/BN, cT/BM, cB), thr>>>(pQ, pK, pS, cT, cT, cE, cE, cE, cT,
                                             (long long)cT*cE, (long long)cT*cE,
                                             (long long)cT*cT, 1);
    softmax_kernel<<<MT/8, 256>>>(lengths);

    // AH_b = P_b @ V_b (causal k-limit)
    gemm_nn<<<dim3(cE/BN, cT/BM, cB), thr>>>(pS, pV, pAH, cT, cE, cT, cT, cE, cE,
                                             (long long)cT*cT, (long long)cT*cE,
                                             (long long)cT*cE, 1);

    wow1_kernel<<<cE, cHID>>>(Wo, W1);
    db_kernel<<<cB, cHID>>>(dest, emb, W1);
    consts_kernel<<<1, 128>>>(distW, distb, dirW, dirb, ttW, ttb, obW1, omb1, W1);

    // Hc = AH @ (Wo @ W1[:128])
    gemm_nn<<<dim3(2, MT/BM, 1), thr>>>(pAH, pWoW1, pHc, MT, cHID, cE, cE, cHID, cHID,
                                        0, 0, 0, 0);

    stats_kernel<<<cB, 256>>>(xs, lengths, adj, seg, TD, stp);
    fin_stats_kernel<<<1, 1>>>();

    mlp_kernel<<<dim3(cTM1, cB), 256>>>(xs, lengths, acts, dest, adj, seg, stp, loc, TD,
                                        W2, b2, W3, b3, obb1, obW2, obb2);
    final_kernel<<<1, 64>>>(lengths, (float*)d_out);
}